// round 1
// baseline (speedup 1.0000x reference)
#include <cuda_runtime.h>
#include <cstdint>
#include <cstddef>

#define Lc   1024
#define Mc   128
#define Bc   8192
#define CC   64          // steps per smem chunk
#define BPB  32          // batches per block
#define ES_ROW 320       // padded words per step: 16 chunks * 20 words
#define HALF 512

// Transposed epsilon: epsT[i*256 + d*128 + m]
__device__ float g_epsT[Lc * 256];

__global__ void transpose_eps_kernel(const float* __restrict__ eps) {
    int idx = blockIdx.x * blockDim.x + threadIdx.x;   // idx = i*256 + dm
    if (idx < Lc * 256) {
        int dm = idx & 255;
        int i  = idx >> 8;
        g_epsT[idx] = eps[(dm << 10) + i];             // eps[(d*128+m)*1024 + i]
    }
}

static __device__ __forceinline__ uint64_t mul2(uint64_t a, uint64_t b) {
    uint64_t d;
    asm("mul.rn.f32x2 %0, %1, %2;" : "=l"(d) : "l"(a), "l"(b));
    return d;
}
static __device__ __forceinline__ uint64_t fma2(uint64_t a, uint64_t b, uint64_t c) {
    uint64_t d;
    asm("fma.rn.f32x2 %0, %1, %2, %3;" : "=l"(d) : "l"(a), "l"(b), "l"(c));
    return d;
}
static __device__ __forceinline__ float hadd2(uint64_t v) {
    float x, y;
    asm("mov.b64 {%0,%1}, %2;" : "=f"(x), "=f"(y) : "l"(v));
    return x + y;
}
static __device__ __forceinline__ float ex2f(float x) {
    float y; asm("ex2.approx.ftz.f32 %0, %1;" : "=f"(y) : "f"(x)); return y;
}
static __device__ __forceinline__ float lg2f(float x) {
    float y; asm("lg2.approx.ftz.f32 %0, %1;" : "=f"(y) : "f"(x)); return y;
}

__global__ __launch_bounds__(256, 2)
void arqgps_kernel(const int* __restrict__ inputs, float* __restrict__ out) {
    extern __shared__ float smemf[];
    float* es = smemf;                             // CC*ES_ROW floats (80 KB)
    int*   xs = (int*)(smemf + CC * ES_ROW);       // CC*BPB ints (8 KB)

    const int t  = threadIdx.x;
    const int w  = t >> 5;
    const int l  = t & 31;
    const int bi = l >> 3;          // batch within warp (0..3)
    const int q  = l & 7;           // m-chunk within batch (0..7), m = q*16..q*16+15
    const int bLocal = (w << 2) | bi;
    const int b0 = blockIdx.x * BPB;

    const uint64_t ONE2 = 0x3f8000003f800000ull;   // {1.0f, 1.0f}
    uint64_t g[8];
#pragma unroll
    for (int k = 0; k < 8; k++) g[k] = ONE2;

    float acc = 0.0f;
    int cnt0 = 0;                                   // count of x_j == 0 for j < i

    for (int chunk = 0; chunk < Lc / CC; chunk++) {
        __syncthreads();
        // ---- stage epsilon chunk (coalesced gmem, padded smem layout) ----
        {
            const float* src = g_epsT + chunk * (CC * 256);
#pragma unroll
            for (int it = 0; it < (CC * 256 / 4) / 256; it++) {   // 16 iters
                int lin4 = t + (it << 8);
                int s = lin4 << 2;                 // word index in chunk
                int i = s >> 8;
                int rem = s & 255;                 // d*128 + q*16 + r
                float4 v = *(const float4*)(src + s);
                *(float4*)(es + i * ES_ROW + (rem >> 4) * 20 + (rem & 15)) = v;
            }
        }
        // ---- stage inputs chunk: xs[i][bLocal] ----
#pragma unroll
        for (int it = 0; it < 2; it++) {
            int idx = (t << 1) | it;               // int4 index 0..511
            int bl = idx >> 4;                     // 0..31
            int j  = idx & 15;                     // int4 within row
            const int4 v = *(const int4*)(inputs + (size_t)(b0 + bl) * Lc
                                          + chunk * CC + (j << 2));
            xs[((j << 2) + 0) * BPB + bl] = v.x;
            xs[((j << 2) + 1) * BPB + bl] = v.y;
            xs[((j << 2) + 2) * BPB + bl] = v.z;
            xs[((j << 2) + 3) * BPB + bl] = v.w;
        }
        __syncthreads();

#pragma unroll 2
        for (int ii = 0; ii < CC; ii++) {
            const float* bp = es + ii * ES_ROW + q * 20;

            uint64_t e0[8], e1[8];
#pragma unroll
            for (int k = 0; k < 4; k++) {
                ulonglong2 va = *(const ulonglong2*)(bp + 4 * k);
                e0[2 * k]     = va.x;
                e0[2 * k + 1] = va.y;
                ulonglong2 vb = *(const ulonglong2*)(bp + 160 + 4 * k);
                e1[2 * k]     = vb.x;
                e1[2 * k + 1] = vb.y;
            }

            // dots against g (g = prod_{j<i} eps[x_j,:,j] for this lane's m-range)
            uint64_t s0p = mul2(e0[0], g[0]);
            uint64_t s1p = mul2(e1[0], g[0]);
#pragma unroll
            for (int k = 1; k < 8; k++) {
                s0p = fma2(e0[k], g[k], s0p);
                s1p = fma2(e1[k], g[k], s1p);
            }

            int xi = xs[ii * BPB + bLocal];        // inputs[b, i], uniform per 8-lane group

            // g update for next step (independent of reduction -> overlaps)
#pragma unroll
            for (int k = 0; k < 8; k++) {
                uint64_t m = xi ? e1[k] : e0[k];
                g[k] = mul2(g[k], m);
            }

            float s0 = hadd2(s0p);
            float s1 = hadd2(s1p);
#pragma unroll
            for (int off = 1; off <= 4; off <<= 1) {
                s0 += __shfl_xor_sync(0xffffffffu, s0, off);
                s1 += __shfl_xor_sync(0xffffffffu, s1, off);
            }

            // term = lp_sel - max - 0.5*log(1 + exp(-2*|lp0-lp1|)); 0 if other exhausted
            float lps = xi ? s1 : s0;
            float mx  = fmaxf(s0, s1);
            float d   = fabsf(s0 - s1);
            float z   = ex2f(d * -2.8853902f);      // exp(-2d) via ex2
            float lg  = lg2f(1.0f + z);
            float term = (lps - mx) - 0.34657359f * lg;

            int i = chunk * CC + ii;
            int cOther = xi ? cnt0 : (i - cnt0);    // consumed so far = i
            if (cOther >= HALF) term = 0.0f;
            acc += term;
            cnt0 += (xi ^ 1);
        }
    }

    if (q == 0) out[b0 + bLocal] = acc;
}

extern "C" void kernel_launch(void* const* d_in, const int* in_sizes, int n_in,
                              void* d_out, int out_size) {
    (void)n_in; (void)out_size;
    // Disambiguate input order by element count (inputs: 8.4M ints, epsilon: 262144 floats)
    const int*   inputs;
    const float* eps;
    if (in_sizes[0] == Bc * Lc) {
        inputs = (const int*)d_in[0];
        eps    = (const float*)d_in[1];
    } else {
        inputs = (const int*)d_in[1];
        eps    = (const float*)d_in[0];
    }
    float* out = (float*)d_out;

    transpose_eps_kernel<<<(Lc * 256) / 256, 256>>>(eps);

    size_t smem = (size_t)CC * ES_ROW * 4 + (size_t)CC * BPB * 4;   // 90112 B
    cudaFuncSetAttribute(arqgps_kernel,
                         cudaFuncAttributeMaxDynamicSharedMemorySize, (int)smem);
    arqgps_kernel<<<Bc / BPB, 256, smem>>>(inputs, out);
}